// round 14
// baseline (speedup 1.0000x reference)
#include <cuda_runtime.h>
#include <cuda_bf16.h>
#include <cstdint>

// PCEN: M_t = (1-s) M_{t-1} + s x_t  (per [b,f] row along T),
// out = (x / (EPS + M)^alpha + bias)^power - bias^power
//
// One CTA (128 thr) per row of T=2048; 16 elems/thread.
// R12: packed f32x2 math. Each thread's 16 elems split into two parallel
// 8-chains (seam state m_mid = c8*m_in + b0 from the pre-pass), all
// non-MUFU float ops run as fma/mul/add.rn.f32x2 (one issue slot per 2 elems).
// cp.async GMEM->SMEM staging, padded tile, coalesced LDG/STG (R11 base).

#define T_LEN 2048
#define NTHREADS 128
#define PER_THREAD 16
#define NWARPS (NTHREADS / 32)
#define ROW_F4 (T_LEN / 4)                 // 512 float4 per row
#define PAD_SLOT(k) ((k) + ((k) >> 3))     // 1 pad float4 per 8
#define TILE_F4 (ROW_F4 + (ROW_F4 >> 3))   // 576

__device__ __forceinline__ float fast_lg2(float x) {
    float r;
    asm("lg2.approx.f32 %0, %1;" : "=f"(r) : "f"(x));
    return r;
}
__device__ __forceinline__ float fast_ex2(float x) {
    float r;
    asm("ex2.approx.f32 %0, %1;" : "=f"(r) : "f"(x));
    return r;
}
__device__ __forceinline__ unsigned int smem_u32(const void* p) {
    unsigned int a;
    asm("{ .reg .u64 t; cvta.to.shared.u64 t, %1; cvt.u32.u64 %0, t; }"
        : "=r"(a) : "l"(p));
    return a;
}

// ---- packed f32x2 helpers (Blackwell) ----
typedef unsigned long long f32x2;
__device__ __forceinline__ f32x2 pk(float lo, float hi) {
    f32x2 r;
    asm("mov.b64 %0, {%1, %2};" : "=l"(r) : "f"(lo), "f"(hi));
    return r;
}
__device__ __forceinline__ void upk(f32x2 v, float& lo, float& hi) {
    asm("mov.b64 {%0, %1}, %2;" : "=f"(lo), "=f"(hi) : "l"(v));
}
__device__ __forceinline__ f32x2 ffma2(f32x2 a, f32x2 b, f32x2 c) {
    f32x2 r;
    asm("fma.rn.f32x2 %0, %1, %2, %3;" : "=l"(r) : "l"(a), "l"(b), "l"(c));
    return r;
}
__device__ __forceinline__ f32x2 fmul2(f32x2 a, f32x2 b) {
    f32x2 r;
    asm("mul.rn.f32x2 %0, %1, %2;" : "=l"(r) : "l"(a), "l"(b));
    return r;
}
__device__ __forceinline__ f32x2 fadd2(f32x2 a, f32x2 b) {
    f32x2 r;
    asm("add.rn.f32x2 %0, %1, %2;" : "=l"(r) : "l"(a), "l"(b));
    return r;
}

__global__ __launch_bounds__(NTHREADS, 12)
void pcen_kernel(const float* __restrict__ x,
                 const float* __restrict__ alpha_p,
                 const float* __restrict__ power_p,
                 const float* __restrict__ bias_p,
                 float* __restrict__ out)
{
    const float s  = 0.015f;
    const float c1 = 0.985f;      // 1 - s
    const float EPSv = 1e-9f;

    __shared__ float4 tile[TILE_F4];
    __shared__ float  sW[NWARPS];

    const int tid  = threadIdx.x;
    const int lane = tid & 31;
    const int warp = tid >> 5;

    const size_t base = (size_t)blockIdx.x * T_LEN;
    const float4* xin = (const float4*)(x + base);
    float4* oout = (float4*)(out + base);

    // GMEM -> SMEM via cp.async: coalesced, no register staging.
    #pragma unroll
    for (int j = 0; j < 4; j++) {
        unsigned int dst = smem_u32(&tile[PAD_SLOT(j * NTHREADS + tid)]);
        const float4* src = &xin[j * NTHREADS + tid];
        asm volatile("cp.async.cg.shared.global [%0], [%1], 16;"
                     :: "r"(dst), "l"(src));
    }
    asm volatile("cp.async.commit_group;");

    // Scalars while the copy is in flight.
    const float alpha = __ldg(alpha_p);
    const float power = __ldg(power_p);
    const float bias  = __ldg(bias_p);

    asm volatile("cp.async.wait_group 0;");
    __syncthreads();   // bar1: tile(x) ready

    // Per-thread contiguous chunk: elements [tid*16, tid*16+16).
    float xv[PER_THREAD];
    #pragma unroll
    for (int j = 0; j < 4; j++) {
        float4 t4 = tile[PAD_SLOT(tid * 4 + j)];
        xv[4 * j + 0] = t4.x; xv[4 * j + 1] = t4.y;
        xv[4 * j + 2] = t4.z; xv[4 * j + 3] = t4.w;
    }

    // Packed pre-pass: two independent zero-state 8-chains (lo: 0..7, hi: 8..15).
    const f32x2 c1_2 = pk(c1, c1);
    f32x2 b2 = pk(0.f, 0.f);
    #pragma unroll
    for (int i = 0; i < 8; i++)
        b2 = ffma2(c1_2, b2, pk(xv[i], xv[i + 8]));
    float b0, b1;
    upk(b2, b0, b1);

    // Decay powers.
    const float c2  = c1 * c1;
    const float c4  = c2 * c2;
    const float c8  = c4 * c4;       // c1^8   (per half-segment decay)
    const float a1  = c8 * c8;       // c1^16  (per-thread segment decay A)
    const float a2  = a1 * a1;       // A^2
    const float a4  = a2 * a2;       // A^4
    const float a8  = a4 * a4;       // A^8
    const float a16 = a8 * a8;       // A^16
    const float a32 = a16 * a16;     // A^32 (per-warp decay)

    float B = fmaf(b0, c8, b1);      // thread total

    // Inclusive Kogge-Stone warp scan: v_t = v_{t-d} * A^d + v_t
    float v = B;
    float u;
    u = __shfl_up_sync(0xffffffffu, v, 1);  if (lane >= 1)  v = fmaf(u, a1,  v);
    u = __shfl_up_sync(0xffffffffu, v, 2);  if (lane >= 2)  v = fmaf(u, a2,  v);
    u = __shfl_up_sync(0xffffffffu, v, 4);  if (lane >= 4)  v = fmaf(u, a4,  v);
    u = __shfl_up_sync(0xffffffffu, v, 8);  if (lane >= 8)  v = fmaf(u, a8,  v);
    u = __shfl_up_sync(0xffffffffu, v, 16); if (lane >= 16) v = fmaf(u, a16, v);

    if (lane == 31) sW[warp] = v;
    __syncthreads();   // bar2: sW ready

    // Cross-warp carry, computed redundantly per-thread (broadcast LDS).
    float carry = 0.f;
    #pragma unroll
    for (int w = 0; w < NWARPS - 1; w++)
        if (warp > w) carry = fmaf(carry, a32, sW[w]);

    float prev = __shfl_up_sync(0xffffffffu, v, 1);
    if (lane == 0) prev = 0.f;

    // A^lane by exact binary exponentiation.
    float p = 1.f;
    if (lane & 1)  p *= a1;
    if (lane & 2)  p *= a2;
    if (lane & 4)  p *= a4;
    if (lane & 8)  p *= a8;
    if (lane & 16) p *= a16;

    float m_in = fmaf(carry, p, prev);       // state entering elem 0
    float m_mid = fmaf(c8, m_in, b0);        // state entering elem 8 (linear seam)

    const float nalpha = -alpha;
    const float bp = fast_ex2(power * fast_lg2(bias));   // bias^power

    const f32x2 s2    = pk(s, s);
    const f32x2 eps2  = pk(EPSv, EPSv);
    const f32x2 bias2 = pk(bias, bias);
    const f32x2 na2   = pk(nalpha, nalpha);
    const f32x2 pw2   = pk(power, power);
    const f32x2 nbp2  = pk(-bp, -bp);

    f32x2 m2 = pk(m_in, m_mid);

    // Packed epilogue: lo lane = elems 0..7, hi lane = elems 8..15.
    // Per pair: 2x ffma2 + 2x fmul2 + 1x ffma2 + 1x fadd2 (non-MUFU) + 8 scalar MUFU.
    #pragma unroll
    for (int jj = 0; jj < 2; jj++) {
        float oA[4], oB[4];
        #pragma unroll
        for (int e = 0; e < 4; e++) {
            const int i = jj * 4 + e;
            f32x2 x2 = pk(xv[i], xv[i + 8]);
            m2 = ffma2(c1_2, m2, x2);                 // m' recurrence (both halves)
            f32x2 arg2 = ffma2(s2, m2, eps2);         // EPS + M
            float aLo, aHi; upk(arg2, aLo, aHi);
            f32x2 t2 = fmul2(na2, pk(fast_lg2(aLo), fast_lg2(aHi)));
            float tLo, tHi; upk(t2, tLo, tHi);
            f32x2 inv2 = pk(fast_ex2(tLo), fast_ex2(tHi));   // (EPS+M)^(-alpha)
            f32x2 z2 = ffma2(x2, inv2, bias2);
            float zLo, zHi; upk(z2, zLo, zHi);
            f32x2 w2 = fmul2(pw2, pk(fast_lg2(zLo), fast_lg2(zHi)));
            float wLo, wHi; upk(w2, wLo, wHi);
            f32x2 o2 = fadd2(pk(fast_ex2(wLo), fast_ex2(wHi)), nbp2);
            upk(o2, oA[e], oB[e]);
        }
        float4 t4;
        t4.x = oA[0]; t4.y = oA[1]; t4.z = oA[2]; t4.w = oA[3];
        tile[PAD_SLOT(tid * 4 + jj)] = t4;            // elems jj*4 .. jj*4+3
        t4.x = oB[0]; t4.y = oB[1]; t4.z = oB[2]; t4.w = oB[3];
        tile[PAD_SLOT(tid * 4 + jj + 2)] = t4;        // elems jj*4+8 .. +11
    }
    __syncthreads();   // bar3: tile(o) ready

    oout[0 * NTHREADS + tid] = tile[PAD_SLOT(0 * NTHREADS + tid)];
    oout[1 * NTHREADS + tid] = tile[PAD_SLOT(1 * NTHREADS + tid)];
    oout[2 * NTHREADS + tid] = tile[PAD_SLOT(2 * NTHREADS + tid)];
    oout[3 * NTHREADS + tid] = tile[PAD_SLOT(3 * NTHREADS + tid)];
}

extern "C" void kernel_launch(void* const* d_in, const int* in_sizes, int n_in,
                              void* d_out, int out_size)
{
    const float* x     = (const float*)d_in[0];
    const float* alpha = (const float*)d_in[1];
    const float* power = (const float*)d_in[2];
    const float* bias  = (const float*)d_in[3];
    float* out = (float*)d_out;

    int rows = in_sizes[0] / T_LEN;   // B*F = 16384
    pcen_kernel<<<rows, NTHREADS>>>(x, alpha, power, bias, out);
}